// round 6
// baseline (speedup 1.0000x reference)
#include <cuda_runtime.h>

#define TT 2048
#define BB 64
#define HH 128
#define GG 384
#define MTOT (BB * TT)   // 131072
#define NC 16            // pipeline chunks
#define TCH (TT / NC)    // 128 steps per chunk
#define SMEMG ((64 * 128 + 128 * 128) * 4)

// Scratch (device globals: no runtime allocation allowed)
__device__ float g_gx[(size_t)3 * MTOT * GG];   // per-layer pre-activations
__device__ float g_buf[(size_t)3 * MTOT * HH];  // per-layer outputs
__device__ float g_h[3 * BB * HH];              // chunk-boundary hidden state

// ---------- packed f32x2 helpers (sm_100+ PTX) ----------
__device__ __forceinline__ unsigned long long pk2(float x, float y) {
    unsigned long long r;
    asm("mov.b64 %0, {%1, %2};" : "=l"(r) : "f"(x), "f"(y));
    return r;
}
__device__ __forceinline__ void upk2(unsigned long long v, float& x, float& y) {
    asm("mov.b64 {%0, %1}, %2;" : "=f"(x), "=f"(y) : "l"(v));
}
__device__ __forceinline__ unsigned long long ffma2(unsigned long long a,
                                                    unsigned long long b,
                                                    unsigned long long c) {
    unsigned long long d;
    asm("fma.rn.f32x2 %0, %1, %2, %3;" : "=l"(d) : "l"(a), "l"(b), "l"(c));
    return d;
}
__device__ __forceinline__ float sigm(float x) {
    return 1.0f / (1.0f + __expf(-x));
}
// Named-barrier primitives (whole-warp uniform use only).
__device__ __forceinline__ void bar_sync(int b, int cnt) {
    asm volatile("bar.sync %0, %1;" :: "r"(b), "r"(cnt) : "memory");
}
__device__ __forceinline__ void bar_arrive(int b, int cnt) {
    asm volatile("bar.arrive %0, %1;" :: "r"(b), "r"(cnt) : "memory");
}

// ============================================================================
// Chunked persistent GRU scan, steps [t0, t0+TCH), one CTA per batch row.
// Warp roles: warps 0-7 (c<256) = z/r gate columns; warps 8-11 = h columns.
// Producer/consumer named barriers:
//   bar 1: z/r publish sigmoids  -> h warps consume
//   bar 0: h warps publish h_new -> z/r warps consume
//   bar 2: h warps mutual sync (they read each other's h_new)
// z/r warps' next-step GEMV overlaps h warps' combine/tanh.
// ============================================================================
__global__ void __launch_bounds__(GG, 1) gru_scan(
    const float* __restrict__ gx,    // [B, T, 384]
    const float* __restrict__ rec,   // [128, 384]
    const float* __restrict__ brec,  // [384]
    float* __restrict__ out,         // [B, T, 128]
    float* __restrict__ hstate,      // [B, 128]
    int t0)
{
    __shared__ __align__(16) float h[HH];
    __shared__ float szr[2 * HH];
    __shared__ __align__(16) float sbuf[2][4 * GG];  // 2 x 4-step gx stage

    const int b = blockIdx.x;
    const int c = threadIdx.x;
    const bool is_h = (c >= 2 * HH);

    unsigned long long w2[64];
#pragma unroll
    for (int p = 0; p < 64; ++p)
        w2[p] = pk2(rec[(2 * p) * GG + c], rec[(2 * p + 1) * GG + c]);
    const float brc = brec[c];

    float hreg = 0.0f;
    if (is_h) {
        hreg = (t0 == 0) ? 0.0f : hstate[b * HH + (c - 2 * HH)];
        h[c - 2 * HH] = hreg;
    }

    const float4* gx4b = (const float4*)(gx + (size_t)b * TT * GG);
    ((float4*)sbuf[0])[c] = gx4b[(size_t)t0 * 96 + c];
    float* outp = out + (size_t)b * TT * HH;
    __syncthreads();

    const int tend = t0 + TCH;
    int cur = 0;
    for (int tg = t0; tg < tend; tg += 4) {
        float4 pf;
        const bool havepf = (tg + 4) < tend;
        if (havepf) pf = gx4b[(size_t)(tg + 4) * 96 + c];

#pragma unroll
        for (int k = 0; k < 4; ++k) {
            // GEMV: a = brec[c] + sum_k h[k]*rec[k][c], 4 indep chains
            unsigned long long a0 = pk2(brc, 0.0f);
            unsigned long long a1 = 0ull, a2 = 0ull, a3 = 0ull;
            const ulonglong2* h4 = (const ulonglong2*)h;
#pragma unroll
            for (int j = 0; j < 16; ++j) {
                ulonglong2 p = h4[2 * j];
                ulonglong2 q = h4[2 * j + 1];
                a0 = ffma2(p.x, w2[4 * j + 0], a0);
                a1 = ffma2(p.y, w2[4 * j + 1], a1);
                a2 = ffma2(q.x, w2[4 * j + 2], a2);
                a3 = ffma2(q.y, w2[4 * j + 3], a3);
            }
            float x0, y0, x1, y1, x2, y2, x3, y3;
            upk2(a0, x0, y0); upk2(a1, x1, y1);
            upk2(a2, x2, y2); upk2(a3, x3, y3);
            float a = ((x0 + x1) + (x2 + x3)) + ((y0 + y1) + (y2 + y3));

            const float gxv = sbuf[cur][k * GG + c];

            if (!is_h) {
                szr[c] = sigm(a + gxv);                    // publish z / r
                if (k == 3 && havepf) ((float4*)sbuf[cur ^ 1])[c] = pf;
                bar_arrive(1, 384);                        // release h warps
                bar_sync(0, 384);                          // wait for h_new
            } else {
                bar_sync(1, 384);                          // wait for z / r
                const int cc = c - 2 * HH;
                float z = szr[cc];
                float r = szr[cc + HH];
                float pre = gxv + r * a;
                float cand = 2.0f * sigm(2.0f * pre) - 1.0f;  // tanh
                float hn = fmaf(z, hreg - cand, cand);
                hreg = hn;
                h[cc] = hn;
                outp[(size_t)(tg + k) * HH + cc] = hn;
                if (k == 3 && havepf) ((float4*)sbuf[cur ^ 1])[c] = pf;
                bar_arrive(0, 384);                        // release z/r warps
                bar_sync(2, 128);                          // h warps mutual
            }
        }
        cur ^= 1;
    }

    if (is_h) hstate[b * HH + (c - 2 * HH)] = hreg;
}

// ============================================================================
// fp32 GEMM + bias (+ optional sigmoid), packed f32x2 FMA.
// Chunked: rows (b, t), t in [t0, t0+TCH). TCH=128 -> 2 blocks of 64 rows/b.
// ============================================================================
__global__ void __launch_bounds__(256, 2) gemm_bias(
    const float* __restrict__ A, const float* __restrict__ Bm,
    const float* __restrict__ bias, float* __restrict__ C,
    int N, int do_sig, int t0)
{
    extern __shared__ float smem[];
    float* As = smem;            // [64][128]
    float* Bs = smem + 64 * 128; // [128][128]

    const int tid = threadIdx.x;
    const int nb = blockIdx.x;
    const int m0 = (nb >> 1) * TT + t0 + (nb & 1) * 64;
    const int n0 = blockIdx.y * 128;

    const float4* A4 = (const float4*)(A + (size_t)m0 * 128);
    float4* As4 = (float4*)As;
#pragma unroll
    for (int i = 0; i < 8; ++i) {
        int idx = i * 256 + tid;
        As4[idx] = A4[idx];
    }
    const int N4 = N >> 2;
    const float4* B4 = (const float4*)Bm;
    float4* Bs4 = (float4*)Bs;
#pragma unroll
    for (int i = 0; i < 16; ++i) {
        int idx = i * 256 + tid;
        int k = idx >> 5;
        int c4 = idx & 31;
        Bs4[idx] = B4[(size_t)k * N4 + (n0 >> 2) + c4];
    }
    __syncthreads();

    const int rg = tid >> 4;
    const int cg = tid & 15;

    unsigned long long acc[2][4][2];
#pragma unroll
    for (int hf = 0; hf < 2; ++hf)
#pragma unroll
        for (int i = 0; i < 4; ++i) {
            acc[hf][i][0] = 0ull;
            acc[hf][i][1] = 0ull;
        }

    const ulonglong2* BsU = (const ulonglong2*)Bs;

#pragma unroll 8
    for (int k = 0; k < 128; ++k) {
        ulonglong2 bv0 = BsU[k * 32 + cg];
        ulonglong2 bv1 = BsU[k * 32 + 16 + cg];
        float a0 = As[(rg * 4 + 0) * 128 + k];
        float a1 = As[(rg * 4 + 1) * 128 + k];
        float a2 = As[(rg * 4 + 2) * 128 + k];
        float a3 = As[(rg * 4 + 3) * 128 + k];
        unsigned long long aa0 = pk2(a0, a0);
        unsigned long long aa1 = pk2(a1, a1);
        unsigned long long aa2 = pk2(a2, a2);
        unsigned long long aa3 = pk2(a3, a3);

        acc[0][0][0] = ffma2(aa0, bv0.x, acc[0][0][0]);
        acc[0][0][1] = ffma2(aa0, bv0.y, acc[0][0][1]);
        acc[0][1][0] = ffma2(aa1, bv0.x, acc[0][1][0]);
        acc[0][1][1] = ffma2(aa1, bv0.y, acc[0][1][1]);
        acc[0][2][0] = ffma2(aa2, bv0.x, acc[0][2][0]);
        acc[0][2][1] = ffma2(aa2, bv0.y, acc[0][2][1]);
        acc[0][3][0] = ffma2(aa3, bv0.x, acc[0][3][0]);
        acc[0][3][1] = ffma2(aa3, bv0.y, acc[0][3][1]);
        acc[1][0][0] = ffma2(aa0, bv1.x, acc[1][0][0]);
        acc[1][0][1] = ffma2(aa0, bv1.y, acc[1][0][1]);
        acc[1][1][0] = ffma2(aa1, bv1.x, acc[1][1][0]);
        acc[1][1][1] = ffma2(aa1, bv1.y, acc[1][1][1]);
        acc[1][2][0] = ffma2(aa2, bv1.x, acc[1][2][0]);
        acc[1][2][1] = ffma2(aa2, bv1.y, acc[1][2][1]);
        acc[1][3][0] = ffma2(aa3, bv1.x, acc[1][3][0]);
        acc[1][3][1] = ffma2(aa3, bv1.y, acc[1][3][1]);
    }

#pragma unroll
    for (int hf = 0; hf < 2; ++hf) {
        int col = n0 + hf * 64 + cg * 4;
        float4 bb = *(const float4*)(bias + col);
#pragma unroll
        for (int i = 0; i < 4; ++i) {
            float4 v;
            upk2(acc[hf][i][0], v.x, v.y);
            upk2(acc[hf][i][1], v.z, v.w);
            v.x += bb.x; v.y += bb.y; v.z += bb.z; v.w += bb.w;
            if (do_sig) {
                v.x = sigm(v.x); v.y = sigm(v.y);
                v.z = sigm(v.z); v.w = sigm(v.w);
            }
            *(float4*)(C + (size_t)(m0 + rg * 4 + i) * N + col) = v;
        }
    }
}

// ============================================================================
// Streams + events (created once at load; host objects only, no device mem).
// s[0..2]=scan (HIGH priority), s[3..5]=per-layer gemm, s[6]=out-projection.
// ============================================================================
struct PipeRes {
    cudaStream_t s[7];
    cudaEvent_t fork;
    cudaEvent_t eg[3][NC];   // gemm(l, i) done
    cudaEvent_t es[3][NC];   // scan(l, i) done
    cudaEvent_t tail[7];
    PipeRes() {
        int lo, hi;
        cudaDeviceGetStreamPriorityRange(&lo, &hi);
        for (int i = 0; i < 3; ++i)
            cudaStreamCreateWithPriority(&s[i], cudaStreamNonBlocking, hi);
        for (int i = 3; i < 7; ++i)
            cudaStreamCreateWithPriority(&s[i], cudaStreamNonBlocking, lo);
        cudaEventCreateWithFlags(&fork, cudaEventDisableTiming);
        for (int l = 0; l < 3; ++l)
            for (int i = 0; i < NC; ++i) {
                cudaEventCreateWithFlags(&eg[l][i], cudaEventDisableTiming);
                cudaEventCreateWithFlags(&es[l][i], cudaEventDisableTiming);
            }
        for (int i = 0; i < 7; ++i)
            cudaEventCreateWithFlags(&tail[i], cudaEventDisableTiming);
    }
};
static PipeRes P;

extern "C" void kernel_launch(void* const* d_in, const int* in_sizes, int n_in,
                              void* d_out, int out_size)
{
    const float* X    = (const float*)d_in[0];  // [64,2048,128]
    const float* Wk   = (const float*)d_in[1];  // [128,384]
    const float* Wr   = (const float*)d_in[2];  // [128,384]
    const float* bin  = (const float*)d_in[3];  // [384]
    const float* brec = (const float*)d_in[4];  // [384]
    const float* Wo   = (const float*)d_in[5];  // [128,128]
    const float* bo   = (const float*)d_in[6];  // [128]
    float* out = (float*)d_out;                 // [64,2048,128]

    float *gx, *buf, *hst;
    cudaGetSymbolAddress((void**)&gx,  g_gx);
    cudaGetSymbolAddress((void**)&buf, g_buf);
    cudaGetSymbolAddress((void**)&hst, g_h);

    cudaFuncSetAttribute(gemm_bias, cudaFuncAttributeMaxDynamicSharedMemorySize,
                         SMEMG);

    // Fork capture into worker streams.
    cudaEventRecord(P.fork, 0);
    for (int i = 0; i < 7; ++i) cudaStreamWaitEvent(P.s[i], P.fork, 0);

    const dim3 gg(BB * 2, GG / 128);  // 128 x 3
    const dim3 go(BB * 2, HH / 128);  // 128 x 1

    // Interleaved enqueue, chunk-major. Gemm throttled to 2-chunk lookahead.
    for (int i = 0; i < NC; ++i) {
        for (int l = 0; l < 3; ++l) {
            const float* Ain = (l == 0) ? X : (buf + (size_t)(l - 1) * MTOT * HH);
            float* gxl  = gx  + (size_t)l * MTOT * GG;
            float* bufl = buf + (size_t)l * MTOT * HH;
            float* hl   = hst + (size_t)l * BB * HH;
            cudaStream_t sg = P.s[3 + l];
            cudaStream_t sc = P.s[l];

            if (l > 0) cudaStreamWaitEvent(sg, P.es[l - 1][i], 0);
            if (i >= 2) cudaStreamWaitEvent(sg, P.es[l][i - 2], 0);
            gemm_bias<<<gg, 256, SMEMG, sg>>>(Ain, Wk, bin, gxl, GG, 0, i * TCH);
            cudaEventRecord(P.eg[l][i], sg);

            cudaStreamWaitEvent(sc, P.eg[l][i], 0);
            gru_scan<<<BB, GG, 0, sc>>>(gxl, Wr, brec, bufl, hl, i * TCH);
            cudaEventRecord(P.es[l][i], sc);
        }
        cudaStreamWaitEvent(P.s[6], P.es[2][i], 0);
        gemm_bias<<<go, 256, SMEMG, P.s[6]>>>(buf + (size_t)2 * MTOT * HH,
                                              Wo, bo, out, HH, 1, i * TCH);
    }

    // Join everything back to the default (capturing) stream.
    for (int i = 0; i < 7; ++i) {
        cudaEventRecord(P.tail[i], P.s[i]);
        cudaStreamWaitEvent(0, P.tail[i], 0);
    }
}